// round 16
// baseline (speedup 1.0000x reference)
#include <cuda_runtime.h>
#include <cuda_bf16.h>
#include <math.h>
#include <cstdint>

#define N 4096
#define D 128
#define NCLS 512
#define MAXS 64
#define MAXPR 64
#define ENC_NINF 0x007FFFFFu
#define SSTR 136

typedef unsigned long long ull;
typedef __nv_bfloat16 bf16;

// ---- device scratch ----
__device__ float g_sim[(size_t)N * N];
__device__ float g_reward[N];
__device__ float g_outsum;
__device__ int   g_cntR[NCLS], g_cntL[NCLS];
__device__ int   g_startR[NCLS + 1], g_startL[NCLS + 1];
__device__ int   g_memR[N], g_memL[N];
__device__ unsigned g_nmax[N];
__device__ float g_negsum[N];
__device__ float g_pt[N];
__device__ float g_lposv[(size_t)N * MAXS];
__device__ int   g_lposj[(size_t)N * MAXS];
__device__ int   g_lposn[N];
__device__ bf16 g_colhi[N * D], g_collo[N * D];
__device__ bf16 g_rowhi[N * D], g_rowlo[N * D];

__device__ __forceinline__ unsigned fenc(float x){
    unsigned u = __float_as_uint(x);
    return (u & 0x80000000u) ? ~u : (u | 0x80000000u);
}
__device__ __forceinline__ float fdec(unsigned e){
    unsigned u = (e & 0x80000000u) ? (e & 0x7FFFFFFFu) : ~e;
    return __uint_as_float(u);
}
__device__ __forceinline__ float binval(float s){
    return fminf(fmaxf(fmaf(s, -800.f, 800.f), 0.f), 1600.f);
}
__device__ __forceinline__ uint32_t smem_u32(const void* p){
    uint32_t a;
    asm("{ .reg .u64 t; cvta.to.shared.u64 t, %1; cvt.u32.u64 %0, t; }" : "=r"(a) : "l"(p));
    return a;
}
__device__ __forceinline__ float wredsum(float d){
#pragma unroll
    for (int o = 16; o; o >>= 1) d += __shfl_down_sync(0xffffffffu, d, o);
    return d;
}

// ---------------- prep: block 0 = setup, blocks 1.. = split ----------------
__global__ __launch_bounds__(512) void prep_kernel(
    const int* __restrict__ tr, const int* __restrict__ rl,
    const float* __restrict__ col, const float* __restrict__ row)
{
    int t = threadIdx.x;
    if (blockIdx.x > 0){
        int i = (blockIdx.x - 1) * 512 + t;
        float c = col[i], r = row[i];
        bf16 ch = __float2bfloat16(c);
        bf16 rh = __float2bfloat16(r);
        g_colhi[i] = ch; g_collo[i] = __float2bfloat16(c - __bfloat162float(ch));
        g_rowhi[i] = rh; g_rowlo[i] = __float2bfloat16(r - __bfloat162float(rh));
        return;
    }
    __shared__ int cR[NCLS], cL[NCLS];
    __shared__ int wR[16], wL[16];
    cR[t] = 0; cL[t] = 0;
    if (t == 0) g_outsum = 0.f;
    __syncthreads();
    for (int i = t; i < N; i += 512){
        atomicAdd(&cR[tr[i]], 1);
        atomicAdd(&cL[rl[i]], 1);
        g_nmax[i] = ENC_NINF;
        g_negsum[i] = 0.f;
    }
    __syncthreads();
    int lane = t & 31, warp = t >> 5;
    int vR = cR[t], vL = cL[t];
    g_cntR[t] = vR; g_cntL[t] = vL;
    int sR = vR, sL = vL;
#pragma unroll
    for (int o = 1; o < 32; o <<= 1){
        int uR = __shfl_up_sync(0xffffffffu, sR, o);
        int uL = __shfl_up_sync(0xffffffffu, sL, o);
        if (lane >= o){ sR += uR; sL += uL; }
    }
    if (lane == 31){ wR[warp] = sR; wL[warp] = sL; }
    __syncthreads();
    if (t == 0){
        int rR = 0, rL = 0;
        for (int w = 0; w < 16; w++){
            int a = wR[w], b = wL[w];
            wR[w] = rR; wL[w] = rL;
            rR += a; rL += b;
        }
        g_startR[NCLS] = rR; g_startL[NCLS] = rL;
    }
    __syncthreads();
    int excR = wR[warp] + sR - vR;
    int excL = wL[warp] + sL - vL;
    g_startR[t] = excR; g_startL[t] = excL;
    cR[t] = excR; cL[t] = excL;
    __syncthreads();
    for (int i = t; i < N; i += 512){
        int p = atomicAdd(&cR[tr[i]], 1); g_memR[p] = i;
        int q = atomicAdd(&cL[rl[i]], 1); g_memL[q] = i;
    }
}

// ================= MMA core =================
struct Frag64 { float c0[2][4], c1[2][4], c2[2][4], c3[2][4]; };

#define MMA_BF16(F, mf, nf, A0, A1, A2, A3, B0, B1)                              \
    asm volatile(                                                                \
        "mma.sync.aligned.m16n8k16.row.col.f32.bf16.bf16.f32 "                   \
        "{%0,%1,%2,%3}, {%4,%5,%6,%7}, {%8,%9}, {%0,%1,%2,%3};"                  \
        : "+f"(F.c0[mf][nf]), "+f"(F.c1[mf][nf]),                                \
          "+f"(F.c2[mf][nf]), "+f"(F.c3[mf][nf])                                 \
        : "r"(A0), "r"(A1), "r"(A2), "r"(A3), "r"(B0), "r"(B1))

#define LDSM_X4(R, ADDR)                                                         \
    asm volatile("ldmatrix.sync.aligned.m8n8.x4.shared.b16 {%0,%1,%2,%3}, [%4];" \
        : "=r"((R)[0]), "=r"((R)[1]), "=r"((R)[2]), "=r"((R)[3]) : "r"(ADDR))

__device__ __forceinline__ void mma_tile64(
    Frag64& F,
    const bf16 (*sAh)[SSTR], const bf16 (*sAl)[SSTR],
    const bf16 (*sBh)[SSTR], const bf16 (*sBl)[SSTR],
    int wr, int wc, int lane)
{
#pragma unroll
    for (int mf = 0; mf < 2; mf++)
#pragma unroll
        for (int nf = 0; nf < 4; nf++){
            F.c0[mf][nf] = 0.f; F.c1[mf][nf] = 0.f; F.c2[mf][nf] = 0.f; F.c3[mf][nf] = 0.f;
        }
#pragma unroll
    for (int ks = 0; ks < 8; ks++){
        const int k0 = ks * 16;
        const int arow = wr * 32 + (lane & 15);
        const int acol = k0 + (lane >> 4) * 8;
        const int brow = wc * 32 + ((lane >> 4) & 1) * 8 + (lane & 7);
        const int bcol = k0 + ((lane >> 3) & 1) * 8;

        uint32_t ah[2][4], al[2][4];
        LDSM_X4(ah[0], smem_u32(&sAh[arow][acol]));
        LDSM_X4(ah[1], smem_u32(&sAh[arow + 16][acol]));
        LDSM_X4(al[0], smem_u32(&sAl[arow][acol]));
        LDSM_X4(al[1], smem_u32(&sAl[arow + 16][acol]));

        uint32_t bh[2][4], bl[2][4];
        LDSM_X4(bh[0], smem_u32(&sBh[brow][bcol]));
        LDSM_X4(bh[1], smem_u32(&sBh[brow + 16][bcol]));
        LDSM_X4(bl[0], smem_u32(&sBl[brow][bcol]));
        LDSM_X4(bl[1], smem_u32(&sBl[brow + 16][bcol]));

#pragma unroll
        for (int mf = 0; mf < 2; mf++)
#pragma unroll
            for (int nf = 0; nf < 4; nf++){
                const int n2 = nf >> 1, e = (nf & 1) * 2;
                MMA_BF16(F, mf, nf, ah[mf][0], ah[mf][1], ah[mf][2], ah[mf][3],
                         bh[n2][e], bh[n2][e + 1]);
                MMA_BF16(F, mf, nf, ah[mf][0], ah[mf][1], ah[mf][2], ah[mf][3],
                         bl[n2][e], bl[n2][e + 1]);
                MMA_BF16(F, mf, nf, al[mf][0], al[mf][1], al[mf][2], al[mf][3],
                         bh[n2][e], bh[n2][e + 1]);
            }
    }
}

// smem byte offsets
#define OFF_AH 0
#define OFF_AL (128 * SSTR * 2)
#define OFF_BH (2 * 128 * SSTR * 2)
#define OFF_BL (OFF_BH + 64 * SSTR * 2)
#define OFF_INT (OFF_BH + 2 * 64 * SSTR * 2)
#define G_SMEM (OFF_INT + (128 + 64 + 128 + 128 + 128) * 4)

// ---- sym tile body ----
__device__ __forceinline__ void do_sym(int idx, unsigned char* sm, int tid, int wid, int lane){
    bf16 (*sAh)[SSTR] = (bf16(*)[SSTR])(sm + OFF_AH);
    bf16 (*sAl)[SSTR] = (bf16(*)[SSTR])(sm + OFF_AL);
    bf16 (*sBh)[SSTR] = (bf16(*)[SSTR])(sm + OFF_BH);
    bf16 (*sBl)[SSTR] = (bf16(*)[SSTR])(sm + OFF_BL);

    int b = idx >> 1, half = idx & 1, bx = 0;
    while ((bx + 1) * (bx + 2) / 2 <= b) bx++;
    int by = b - bx * (bx + 1) / 2;
    const int row0 = by * 128;
    const int col0 = bx * 128 + half * 64;

#pragma unroll
    for (int it = 0; it < 8; it++){
        int u = tid + it * 256;
        int r = u >> 4, c = (u & 15) * 8;
        *(float4*)&sAh[r][c] = *(const float4*)&g_colhi[(row0 + r) * D + c];
        *(float4*)&sAl[r][c] = *(const float4*)&g_collo[(row0 + r) * D + c];
    }
#pragma unroll
    for (int it = 0; it < 4; it++){
        int u = tid + it * 256;
        int r = u >> 4, c = (u & 15) * 8;
        *(float4*)&sBh[r][c] = *(const float4*)&g_colhi[(col0 + r) * D + c];
        *(float4*)&sBl[r][c] = *(const float4*)&g_collo[(col0 + r) * D + c];
    }
    __syncthreads();

    const int wr = wid & 3, wc = wid >> 2;
    Frag64 F;
    mma_tile64(F, sAh, sAl, sBh, sBl, wr, wc, lane);

    const int g = lane >> 2, t = lane & 3;
#pragma unroll
    for (int mf = 0; mf < 2; mf++){
        int rA = row0 + wr * 32 + mf * 16 + g;
#pragma unroll
        for (int nf = 0; nf < 4; nf++){
            int cc = col0 + wc * 32 + nf * 8 + 2 * t;
            *(float2*)&g_sim[(size_t)rA * N + cc]       = make_float2(F.c0[mf][nf], F.c1[mf][nf]);
            *(float2*)&g_sim[(size_t)(rA + 8) * N + cc] = make_float2(F.c2[mf][nf], F.c3[mf][nf]);
        }
    }
    if (bx != by){
        float* stg = (float*)(sm + OFF_AH);   // [64][132]
        __syncthreads();
#pragma unroll
        for (int mf = 0; mf < 2; mf++){
            int rr = wr * 32 + mf * 16 + g;
#pragma unroll
            for (int nf = 0; nf < 4; nf++){
                int cc = wc * 32 + nf * 8 + 2 * t;
                stg[(cc    ) * 132 + rr]     = F.c0[mf][nf];
                stg[(cc + 1) * 132 + rr]     = F.c1[mf][nf];
                stg[(cc    ) * 132 + rr + 8] = F.c2[mf][nf];
                stg[(cc + 1) * 132 + rr + 8] = F.c3[mf][nf];
            }
        }
        __syncthreads();
#pragma unroll
        for (int it = 0; it < 8; it++){
            int u = tid + it * 256;
            int r = u >> 5, c4 = (u & 31) * 4;
            float4 v = *(const float4*)&stg[r * 132 + c4];
            *(float4*)&g_sim[(size_t)(col0 + r) * N + row0 + c4] = v;
        }
    }
}

// ---- posdot body (8 rows per block) ----
__device__ __forceinline__ void do_posdot(int idx, unsigned char* sm,
    const int* __restrict__ tc, const float* __restrict__ col, const float* __restrict__ row,
    int tid, int warp, int lane)
{
    float* sA = (float*)sm;   // [8][128]
    const int row0 = idx * 8;
    for (int u = tid; u < 8 * 32; u += 256){
        int r = u >> 5, d4 = u & 31;
        *(float4*)&sA[r * 128 + d4 * 4] = *(const float4*)&col[(size_t)(row0 + r) * D + d4 * 4];
    }
    __syncthreads();

    const int i = row0 + warp;
    const int c = tc[i];
    const int s0 = g_startR[c];
    const int cnt = min(g_startR[c + 1] - s0, MAXS);
    float pm = -INFINITY;
    for (int k = lane; k < cnt; k += 32){
        int j = g_memR[s0 + k];
        const float4* bp = (const float4*)&row[(size_t)j * D];
        float acc = 0.f;
#pragma unroll
        for (int d4 = 0; d4 < 32; d4++){
            float4 av = *(const float4*)&sA[warp * 128 + d4 * 4];
            float4 bv = bp[d4];
            acc += av.x*bv.x + av.y*bv.y + av.z*bv.z + av.w*bv.w;
        }
        g_lposv[(size_t)i * MAXS + k] = acc;
        g_lposj[(size_t)i * MAXS + k] = j;
        if (j != i) pm = fmaxf(pm, acc);
    }
#pragma unroll
    for (int o = 16; o; o >>= 1) pm = fmaxf(pm, __shfl_xor_sync(0xffffffffu, pm, o));
    if (lane == 0){
        g_lposn[i] = cnt;
        g_pt[i] = fmaxf(0.6f, pm) - 0.1f;
    }
}

// ---------------- kernel B: sym GEMM + posdot interleaved ----------------
__global__ __launch_bounds__(256, 2) void sym_pos_kernel(
    const int* __restrict__ tc, const float* __restrict__ col, const float* __restrict__ row)
{
    extern __shared__ __align__(16) unsigned char sm[];
    const int tid = threadIdx.x, wid = tid >> 5, lane = tid & 31;
    const int bid = blockIdx.x;    // 0..1567
    if (bid < 1536){
        int m3 = bid % 3;
        if (m3 == 2){ do_posdot(bid / 3, sm, tc, col, row, tid, wid, lane); return; }
        do_sym((bid / 3) * 2 + m3, sm, tid, wid, lane);
    } else {
        do_sym(1024 + (bid - 1536), sm, tid, wid, lane);
    }
}

// ---- loss gemm tile body ----
__device__ __forceinline__ void do_loss(int idx, unsigned char* sm,
    const int* __restrict__ tc, const int* __restrict__ tr, int tid, int wid, int lane)
{
    bf16 (*sAh)[SSTR] = (bf16(*)[SSTR])(sm + OFF_AH);
    bf16 (*sAl)[SSTR] = (bf16(*)[SSTR])(sm + OFF_AL);
    bf16 (*sBh)[SSTR] = (bf16(*)[SSTR])(sm + OFF_BH);
    bf16 (*sBl)[SSTR] = (bf16(*)[SSTR])(sm + OFF_BL);
    int*   tcs = (int*)(sm + OFF_INT);
    int*   trs = tcs + 128;
    unsigned* nme = (unsigned*)(trs + 64);
    float* pts  = (float*)(nme + 128);
    float* lsum = pts + 128;

    const int row0 = (idx >> 6) * 128;
    const int col0 = (idx & 63) * 64;

    if (tid < 128){
        tcs[tid] = tc[row0 + tid];
        nme[tid] = ENC_NINF;
        pts[tid] = g_pt[row0 + tid];
        lsum[tid] = 0.f;
        if (tid < 64) trs[tid] = tr[col0 + tid];
    }
#pragma unroll
    for (int it = 0; it < 8; it++){
        int u = tid + it * 256;
        int r = u >> 4, c = (u & 15) * 8;
        *(float4*)&sAh[r][c] = *(const float4*)&g_colhi[(row0 + r) * D + c];
        *(float4*)&sAl[r][c] = *(const float4*)&g_collo[(row0 + r) * D + c];
    }
#pragma unroll
    for (int it = 0; it < 4; it++){
        int u = tid + it * 256;
        int r = u >> 4, c = (u & 15) * 8;
        *(float4*)&sBh[r][c] = *(const float4*)&g_rowhi[(col0 + r) * D + c];
        *(float4*)&sBl[r][c] = *(const float4*)&g_rowlo[(col0 + r) * D + c];
    }
    __syncthreads();

    const int wr = wid & 3, wc = wid >> 2;
    Frag64 F;
    mma_tile64(F, sAh, sAl, sBh, sBl, wr, wc, lane);

    const int g = lane >> 2, t = lane & 3;
    int lab[8];
#pragma unroll
    for (int nf = 0; nf < 4; nf++){
        lab[nf*2]   = trs[wc * 32 + nf * 8 + 2 * t];
        lab[nf*2+1] = trs[wc * 32 + nf * 8 + 2 * t + 1];
    }
#pragma unroll
    for (int mf = 0; mf < 2; mf++){
#pragma unroll
        for (int hf = 0; hf < 2; hf++){
            int lrow = wr * 32 + mf * 16 + hf * 8 + g;
            int tcv  = tcs[lrow];
            float pt = pts[lrow];
            float nm = -INFINITY, ss = 0.f;
#pragma unroll
            for (int nf = 0; nf < 4; nf++){
                float v0 = hf ? F.c2[mf][nf] : F.c0[mf][nf];
                float v1 = hf ? F.c3[mf][nf] : F.c1[mf][nf];
                if (lab[nf*2]   != tcv) nm = fmaxf(nm, v0);
                if (lab[nf*2+1] != tcv) nm = fmaxf(nm, v1);
                if (v0 > pt) ss += v0;
                if (v1 > pt) ss += v1;
            }
            nm = fmaxf(nm, __shfl_down_sync(0xffffffffu, nm, 1));
            nm = fmaxf(nm, __shfl_down_sync(0xffffffffu, nm, 2));
            ss += __shfl_down_sync(0xffffffffu, ss, 1);
            ss += __shfl_down_sync(0xffffffffu, ss, 2);
            if (t == 0){
                atomicMax(&nme[lrow], fenc(nm));
                atomicAdd(&lsum[lrow], ss);
            }
        }
    }
    __syncthreads();
    if (tid < 128){
        atomicMax(&g_nmax[row0 + tid], nme[tid]);
        atomicAdd(&g_negsum[row0 + tid], lsum[tid]);
    }
}

// ---- reward body (one row) ----
__device__ __forceinline__ void do_reward(int i, const int* __restrict__ rl,
                                          int tid, int lane)
{
    __shared__ float tP[MAXPR];
    __shared__ float qv[2 * MAXPR + 8];
    __shared__ float sQ[2 * MAXPR + 8];
    __shared__ int   np_s;
    __shared__ float s_ap;

    const int c = rl[i];
    const float* row = g_sim + (size_t)i * N;

    if (tid == 0){ np_s = 0; s_ap = 0.f; }
    if (tid < 2 * MAXPR + 8){ sQ[tid] = 0.f; qv[tid] = -1e30f; }
    __syncthreads();

    {
        int s0 = g_startL[c], cnt = g_startL[c + 1] - s0;
        if (tid < cnt){
            int j = g_memL[s0 + tid];
            if (j != i){
                float t = binval(row[j]);
                int k = atomicAdd(&np_s, 1);
                if (k < MAXPR){
                    tP[k] = t;
                    float e = floorf(t);
                    qv[2*k]   = e + 1.0f;
                    qv[2*k+1] = e + 2.0f;
                }
            }
        }
    }
    __syncthreads();
    const int npos = min(np_s, MAXPR);
    const int K8 = (2 * npos + 7) & ~7;

    float t[16];
#pragma unroll
    for (int it = 0; it < 4; it++){
        int j4 = tid + it * 256;
        float4 v = *((const float4*)row + j4);
        int j = j4 * 4;
        t[it*4+0] = (j+0 == i) ? 1e30f : binval(v.x);
        t[it*4+1] = (j+1 == i) ? 1e30f : binval(v.y);
        t[it*4+2] = (j+2 == i) ? 1e30f : binval(v.z);
        t[it*4+3] = (j+3 == i) ? 1e30f : binval(v.w);
    }

    for (int k = 0; k < K8; k += 8){
        float q[8], a[8], b[8];
#pragma unroll
        for (int j = 0; j < 8; j++){ q[j] = qv[k + j]; a[j] = 0.f; b[j] = 0.f; }
#pragma unroll
        for (int m = 0; m < 16; m += 2){
#pragma unroll
            for (int j = 0; j < 8; j++){
                a[j] += __saturatef(q[j] - t[m]);
                b[j] += __saturatef(q[j] - t[m + 1]);
            }
        }
#pragma unroll
        for (int j = 0; j < 8; j++) a[j] += b[j];
        // 3-stage reduce, then lanes 0-3 commit partials via atomics
#pragma unroll
        for (int o = 16; o >= 4; o >>= 1){
#pragma unroll
            for (int j = 0; j < 8; j++)
                a[j] += __shfl_down_sync(0xffffffffu, a[j], o);
        }
        if (lane < 4){
#pragma unroll
            for (int j = 0; j < 8; j++) atomicAdd(&sQ[k + j], a[j]);
        }
    }
    __syncthreads();

    if (tid < npos){
        float tp = tP[tid];
        float e  = floorf(tp);
        float fr = tp - e;
        float u0 = e + 1.0f, u1 = e + 2.0f;
        float HP0 = 0.f, HP1 = 0.f;
        for (int q = 0; q < npos; q++){
            float tq = tP[q];
            HP0 += __saturatef(u0 - tq);
            HP1 += __saturatef(u1 - tq);
        }
        float HA0 = sQ[2*tid], HA1 = sQ[2*tid+1];
        float term = 0.f;
        if (HA0 > 0.f) term += (1.0f - fr) * HP0 / HA0;
        if (fr > 0.f && HA1 > 0.f) term += fr * HP1 / HA1;
        atomicAdd(&s_ap, term);
    }
    __syncthreads();
    if (tid == 0){
        int np = g_cntL[c] - 1;
        g_reward[i] = (np > 0) ? s_ap / (float)np : 0.f;
    }
}

// ---------------- mega kernel: loss GEMM + reward interleaved 1:2 ----------------
__global__ __launch_bounds__(256, 2) void mega_kernel(
    const int* __restrict__ tc, const int* __restrict__ tr, const int* __restrict__ rl)
{
    extern __shared__ __align__(16) unsigned char sm[];
    const int tid = threadIdx.x, wid = tid >> 5, lane = tid & 31;
    const int bid = blockIdx.x;    // 0..6143
    const int m3 = bid % 3;
    if (m3 == 0){
        do_loss(bid / 3, sm, tc, tr, tid, wid, lane);
    } else {
        do_reward((bid / 3) * 2 + m3 - 1, rl, tid, lane);
    }
}

// ---------------- finish: loss fix + weighted accumulate ----------------
__global__ __launch_bounds__(256) void finish_kernel(
    const int* __restrict__ tc, const int* __restrict__ tr)
{
    const int warp = threadIdx.x >> 5, lane = threadIdx.x & 31;
    const int i = blockIdx.x * 8 + warp;
    float nthr = fdec(g_nmax[i]) + 0.1f;
    float pt   = g_pt[i];
    int   ns   = g_lposn[i];
    float fix = 0.f;
    for (int k = lane; k < ns; k += 32){
        float v = g_lposv[(size_t)i * MAXS + k];
        int   j = g_lposj[(size_t)i * MAXS + k];
        if (v > pt) fix -= v;
        if (j != i && v < nthr) fix += 1.0f - v;
    }
    fix = wredsum(fix);
    if (lane == 0){
        int c = tc[i];
        int npos = g_cntR[c] - ((tr[i] == c) ? 1 : 0);
        float loss = (npos > 0) ? g_negsum[i] + fix : 0.f;
        atomicAdd(&g_outsum, loss * (1.0f - g_reward[i]));
    }
}

// ---------------- final scalar ----------------
__global__ void final_kernel(float* __restrict__ out){
    out[0] = g_outsum / (float)N;
}

// ---------------- launch ----------------
extern "C" void kernel_launch(void* const* d_in, const int* in_sizes, int n_in,
                              void* d_out, int out_size)
{
    const float* inputs_col    = (const float*)d_in[0];
    const int*   targets_col   = (const int*)  d_in[1];
    const float* inputs_row    = (const float*)d_in[2];
    const int*   targets_row   = (const int*)  d_in[3];
    const int*   reward_labels = (const int*)  d_in[4];
    float* out = (float*)d_out;

    cudaFuncSetAttribute(sym_pos_kernel, cudaFuncAttributeMaxDynamicSharedMemorySize, G_SMEM);
    cudaFuncSetAttribute(mega_kernel,    cudaFuncAttributeMaxDynamicSharedMemorySize, G_SMEM);

    prep_kernel<<<1025, 512>>>(targets_row, reward_labels, inputs_col, inputs_row);
    sym_pos_kernel<<<1568, 256, G_SMEM>>>(targets_col, inputs_col, inputs_row);
    mega_kernel<<<6144, 256, G_SMEM>>>(targets_col, targets_row, reward_labels);
    finish_kernel<<<512, 256>>>(targets_col, targets_row);
    final_kernel<<<1, 1>>>(out);
}

// round 17
// speedup vs baseline: 1.8340x; 1.8340x over previous
#include <cuda_runtime.h>
#include <cuda_bf16.h>
#include <math.h>
#include <cstdint>

#define N 4096
#define D 128
#define NCLS 512
#define MAXS 64
#define MAXPR 64
#define ENC_NINF 0x007FFFFFu
#define SSTR 136

typedef unsigned long long ull;
typedef __nv_bfloat16 bf16;

// ---- device scratch ----
__device__ float g_sim[(size_t)N * N];
__device__ float g_reward[N];
__device__ float g_outsum;
__device__ int   g_cntR[NCLS], g_cntL[NCLS];
__device__ int   g_startR[NCLS + 1], g_startL[NCLS + 1];
__device__ int   g_memR[N], g_memL[N];
__device__ unsigned g_nmax[N];
__device__ float g_negsum[N];
__device__ float g_pt[N];
__device__ float g_lposv[(size_t)N * MAXS];
__device__ int   g_lposj[(size_t)N * MAXS];
__device__ int   g_lposn[N];
__device__ bf16 g_colhi[N * D], g_collo[N * D];
__device__ bf16 g_rowhi[N * D], g_rowlo[N * D];

__device__ __forceinline__ unsigned fenc(float x){
    unsigned u = __float_as_uint(x);
    return (u & 0x80000000u) ? ~u : (u | 0x80000000u);
}
__device__ __forceinline__ float fdec(unsigned e){
    unsigned u = (e & 0x80000000u) ? (e & 0x7FFFFFFFu) : ~e;
    return __uint_as_float(u);
}
__device__ __forceinline__ float binval(float s){
    return fminf(fmaxf(fmaf(s, -800.f, 800.f), 0.f), 1600.f);
}
__device__ __forceinline__ uint32_t smem_u32(const void* p){
    uint32_t a;
    asm("{ .reg .u64 t; cvta.to.shared.u64 t, %1; cvt.u32.u64 %0, t; }" : "=r"(a) : "l"(p));
    return a;
}
__device__ __forceinline__ float wredsum(float d){
#pragma unroll
    for (int o = 16; o; o >>= 1) d += __shfl_down_sync(0xffffffffu, d, o);
    return d;
}

// ---------------- prep: block 0 = setup, blocks 1.. = split ----------------
__global__ __launch_bounds__(512) void prep_kernel(
    const int* __restrict__ tr, const int* __restrict__ rl,
    const float* __restrict__ col, const float* __restrict__ row)
{
    int t = threadIdx.x;
    if (blockIdx.x > 0){
        int i = (blockIdx.x - 1) * 512 + t;
        float c = col[i], r = row[i];
        bf16 ch = __float2bfloat16(c);
        bf16 rh = __float2bfloat16(r);
        g_colhi[i] = ch; g_collo[i] = __float2bfloat16(c - __bfloat162float(ch));
        g_rowhi[i] = rh; g_rowlo[i] = __float2bfloat16(r - __bfloat162float(rh));
        return;
    }
    __shared__ int cR[NCLS], cL[NCLS];
    __shared__ int wR[16], wL[16];
    cR[t] = 0; cL[t] = 0;
    if (t == 0) g_outsum = 0.f;
    __syncthreads();
    for (int i = t; i < N; i += 512){
        atomicAdd(&cR[tr[i]], 1);
        atomicAdd(&cL[rl[i]], 1);
        g_nmax[i] = ENC_NINF;
        g_negsum[i] = 0.f;
    }
    __syncthreads();
    int lane = t & 31, warp = t >> 5;
    int vR = cR[t], vL = cL[t];
    g_cntR[t] = vR; g_cntL[t] = vL;
    int sR = vR, sL = vL;
#pragma unroll
    for (int o = 1; o < 32; o <<= 1){
        int uR = __shfl_up_sync(0xffffffffu, sR, o);
        int uL = __shfl_up_sync(0xffffffffu, sL, o);
        if (lane >= o){ sR += uR; sL += uL; }
    }
    if (lane == 31){ wR[warp] = sR; wL[warp] = sL; }
    __syncthreads();
    if (t == 0){
        int rR = 0, rL = 0;
        for (int w = 0; w < 16; w++){
            int a = wR[w], b = wL[w];
            wR[w] = rR; wL[w] = rL;
            rR += a; rL += b;
        }
        g_startR[NCLS] = rR; g_startL[NCLS] = rL;
    }
    __syncthreads();
    int excR = wR[warp] + sR - vR;
    int excL = wL[warp] + sL - vL;
    g_startR[t] = excR; g_startL[t] = excL;
    cR[t] = excR; cL[t] = excL;
    __syncthreads();
    for (int i = t; i < N; i += 512){
        int p = atomicAdd(&cR[tr[i]], 1); g_memR[p] = i;
        int q = atomicAdd(&cL[rl[i]], 1); g_memL[q] = i;
    }
}

// ---------------- posdot_loss: pair-parallel ----------------
__global__ __launch_bounds__(256) void posdot_loss(const int* __restrict__ tc,
                            const float* __restrict__ col, const float* __restrict__ row){
    __shared__ float sA[8][128];
    const int warp = threadIdx.x >> 5, lane = threadIdx.x & 31;
    const int tid = threadIdx.x;
    const int row0 = blockIdx.x * 8;

    for (int u = tid; u < 8 * 32; u += 256){
        int r = u >> 5, d4 = u & 31;
        *(float4*)&sA[r][d4 * 4] = *(const float4*)&col[(size_t)(row0 + r) * D + d4 * 4];
    }
    __syncthreads();

    const int i = row0 + warp;
    const int c = tc[i];
    const int s0 = g_startR[c];
    const int cnt = min(g_startR[c + 1] - s0, MAXS);
    float pm = -INFINITY;
    for (int k = lane; k < cnt; k += 32){
        int j = g_memR[s0 + k];
        const float4* bp = (const float4*)&row[(size_t)j * D];
        float acc = 0.f;
#pragma unroll
        for (int d4 = 0; d4 < 32; d4++){
            float4 av = *(const float4*)&sA[warp][d4 * 4];
            float4 bv = bp[d4];
            acc += av.x*bv.x + av.y*bv.y + av.z*bv.z + av.w*bv.w;
        }
        g_lposv[(size_t)i * MAXS + k] = acc;
        g_lposj[(size_t)i * MAXS + k] = j;
        if (j != i) pm = fmaxf(pm, acc);
    }
#pragma unroll
    for (int o = 16; o; o >>= 1) pm = fmaxf(pm, __shfl_xor_sync(0xffffffffu, pm, o));
    if (lane == 0){
        g_lposn[i] = cnt;
        g_pt[i] = fmaxf(0.6f, pm) - 0.1f;
    }
}

// ================= MMA core =================
struct Frag64 { float c0[2][4], c1[2][4], c2[2][4], c3[2][4]; };

#define MMA_BF16(F, mf, nf, A0, A1, A2, A3, B0, B1)                              \
    asm volatile(                                                                \
        "mma.sync.aligned.m16n8k16.row.col.f32.bf16.bf16.f32 "                   \
        "{%0,%1,%2,%3}, {%4,%5,%6,%7}, {%8,%9}, {%0,%1,%2,%3};"                  \
        : "+f"(F.c0[mf][nf]), "+f"(F.c1[mf][nf]),                                \
          "+f"(F.c2[mf][nf]), "+f"(F.c3[mf][nf])                                 \
        : "r"(A0), "r"(A1), "r"(A2), "r"(A3), "r"(B0), "r"(B1))

#define LDSM_X4(R, ADDR)                                                         \
    asm volatile("ldmatrix.sync.aligned.m8n8.x4.shared.b16 {%0,%1,%2,%3}, [%4];" \
        : "=r"((R)[0]), "=r"((R)[1]), "=r"((R)[2]), "=r"((R)[3]) : "r"(ADDR))

__device__ __forceinline__ void mma_tile64(
    Frag64& F,
    const bf16 (*sAh)[SSTR], const bf16 (*sAl)[SSTR],
    const bf16 (*sBh)[SSTR], const bf16 (*sBl)[SSTR],
    int wr, int wc, int lane)
{
#pragma unroll
    for (int mf = 0; mf < 2; mf++)
#pragma unroll
        for (int nf = 0; nf < 4; nf++){
            F.c0[mf][nf] = 0.f; F.c1[mf][nf] = 0.f; F.c2[mf][nf] = 0.f; F.c3[mf][nf] = 0.f;
        }
#pragma unroll
    for (int ks = 0; ks < 8; ks++){
        const int k0 = ks * 16;
        const int arow = wr * 32 + (lane & 15);
        const int acol = k0 + (lane >> 4) * 8;
        const int brow = wc * 32 + ((lane >> 4) & 1) * 8 + (lane & 7);
        const int bcol = k0 + ((lane >> 3) & 1) * 8;

        uint32_t ah[2][4], al[2][4];
        LDSM_X4(ah[0], smem_u32(&sAh[arow][acol]));
        LDSM_X4(ah[1], smem_u32(&sAh[arow + 16][acol]));
        LDSM_X4(al[0], smem_u32(&sAl[arow][acol]));
        LDSM_X4(al[1], smem_u32(&sAl[arow + 16][acol]));

        uint32_t bh[2][4], bl[2][4];
        LDSM_X4(bh[0], smem_u32(&sBh[brow][bcol]));
        LDSM_X4(bh[1], smem_u32(&sBh[brow + 16][bcol]));
        LDSM_X4(bl[0], smem_u32(&sBl[brow][bcol]));
        LDSM_X4(bl[1], smem_u32(&sBl[brow + 16][bcol]));

#pragma unroll
        for (int mf = 0; mf < 2; mf++)
#pragma unroll
            for (int nf = 0; nf < 4; nf++){
                const int n2 = nf >> 1, e = (nf & 1) * 2;
                MMA_BF16(F, mf, nf, ah[mf][0], ah[mf][1], ah[mf][2], ah[mf][3],
                         bh[n2][e], bh[n2][e + 1]);
                MMA_BF16(F, mf, nf, ah[mf][0], ah[mf][1], ah[mf][2], ah[mf][3],
                         bl[n2][e], bl[n2][e + 1]);
                MMA_BF16(F, mf, nf, al[mf][0], al[mf][1], al[mf][2], al[mf][3],
                         bh[n2][e], bh[n2][e + 1]);
            }
    }
}

// smem byte offsets
#define OFF_AH 0
#define OFF_AL (128 * SSTR * 2)
#define OFF_BH (2 * 128 * SSTR * 2)
#define OFF_BL (OFF_BH + 64 * SSTR * 2)
#define OFF_INT (OFF_BH + 2 * 64 * SSTR * 2)
#define GL_SMEM (OFF_INT + (128 + 64 + 128 + 128 + 128) * 4)
#define GS_SMEM OFF_INT

// ---------------- loss GEMM (stream A) ----------------
__global__ __launch_bounds__(256, 2) void gemm_loss(
    const int* __restrict__ tc, const int* __restrict__ tr)
{
    extern __shared__ __align__(16) unsigned char sm[];
    bf16 (*sAh)[SSTR] = (bf16(*)[SSTR])(sm + OFF_AH);
    bf16 (*sAl)[SSTR] = (bf16(*)[SSTR])(sm + OFF_AL);
    bf16 (*sBh)[SSTR] = (bf16(*)[SSTR])(sm + OFF_BH);
    bf16 (*sBl)[SSTR] = (bf16(*)[SSTR])(sm + OFF_BL);
    int*   tcs = (int*)(sm + OFF_INT);
    int*   trs = tcs + 128;
    unsigned* nme = (unsigned*)(trs + 64);
    float* pts  = (float*)(nme + 128);
    float* lsum = pts + 128;

    const int tid  = threadIdx.x;
    const int wid  = tid >> 5;
    const int lane = tid & 31;
    const int row0 = blockIdx.y * 128;
    const int col0 = blockIdx.x * 64;

    if (tid < 128){
        tcs[tid] = tc[row0 + tid];
        nme[tid] = ENC_NINF;
        pts[tid] = g_pt[row0 + tid];
        lsum[tid] = 0.f;
        if (tid < 64) trs[tid] = tr[col0 + tid];
    }
#pragma unroll
    for (int it = 0; it < 8; it++){
        int u = tid + it * 256;
        int r = u >> 4, c = (u & 15) * 8;
        *(float4*)&sAh[r][c] = *(const float4*)&g_colhi[(row0 + r) * D + c];
        *(float4*)&sAl[r][c] = *(const float4*)&g_collo[(row0 + r) * D + c];
    }
#pragma unroll
    for (int it = 0; it < 4; it++){
        int u = tid + it * 256;
        int r = u >> 4, c = (u & 15) * 8;
        *(float4*)&sBh[r][c] = *(const float4*)&g_rowhi[(col0 + r) * D + c];
        *(float4*)&sBl[r][c] = *(const float4*)&g_rowlo[(col0 + r) * D + c];
    }
    __syncthreads();

    const int wr = wid & 3, wc = wid >> 2;
    Frag64 F;
    mma_tile64(F, sAh, sAl, sBh, sBl, wr, wc, lane);

    const int g = lane >> 2, t = lane & 3;
    int lab[8];
#pragma unroll
    for (int nf = 0; nf < 4; nf++){
        lab[nf*2]   = trs[wc * 32 + nf * 8 + 2 * t];
        lab[nf*2+1] = trs[wc * 32 + nf * 8 + 2 * t + 1];
    }
#pragma unroll
    for (int mf = 0; mf < 2; mf++){
#pragma unroll
        for (int hf = 0; hf < 2; hf++){
            int lrow = wr * 32 + mf * 16 + hf * 8 + g;
            int tcv  = tcs[lrow];
            float pt = pts[lrow];
            float nm = -INFINITY, ss = 0.f;
#pragma unroll
            for (int nf = 0; nf < 4; nf++){
                float v0 = hf ? F.c2[mf][nf] : F.c0[mf][nf];
                float v1 = hf ? F.c3[mf][nf] : F.c1[mf][nf];
                if (lab[nf*2]   != tcv) nm = fmaxf(nm, v0);
                if (lab[nf*2+1] != tcv) nm = fmaxf(nm, v1);
                if (v0 > pt) ss += v0;
                if (v1 > pt) ss += v1;
            }
            nm = fmaxf(nm, __shfl_down_sync(0xffffffffu, nm, 1));
            nm = fmaxf(nm, __shfl_down_sync(0xffffffffu, nm, 2));
            ss += __shfl_down_sync(0xffffffffu, ss, 1);
            ss += __shfl_down_sync(0xffffffffu, ss, 2);
            if (t == 0){
                atomicMax(&nme[lrow], fenc(nm));
                atomicAdd(&lsum[lrow], ss);
            }
        }
    }
    __syncthreads();
    if (tid < 128){
        atomicMax(&g_nmax[row0 + tid], nme[tid]);
        atomicAdd(&g_negsum[row0 + tid], lsum[tid]);
    }
}

// ---------------- symmetric GEMM (stream B) ----------------
__global__ __launch_bounds__(256, 2) void gemm_sym(){
    extern __shared__ __align__(16) unsigned char sm[];
    bf16 (*sAh)[SSTR] = (bf16(*)[SSTR])(sm + OFF_AH);
    bf16 (*sAl)[SSTR] = (bf16(*)[SSTR])(sm + OFF_AL);
    bf16 (*sBh)[SSTR] = (bf16(*)[SSTR])(sm + OFF_BH);
    bf16 (*sBl)[SSTR] = (bf16(*)[SSTR])(sm + OFF_BL);

    const int tid  = threadIdx.x;
    const int wid  = tid >> 5;
    const int lane = tid & 31;

    int b = blockIdx.x, bx = 0;
    while ((bx + 1) * (bx + 2) / 2 <= b) bx++;
    int by = b - bx * (bx + 1) / 2;
    const int row0 = by * 128;
    const int col0 = bx * 128 + blockIdx.y * 64;

#pragma unroll
    for (int it = 0; it < 8; it++){
        int u = tid + it * 256;
        int r = u >> 4, c = (u & 15) * 8;
        *(float4*)&sAh[r][c] = *(const float4*)&g_colhi[(row0 + r) * D + c];
        *(float4*)&sAl[r][c] = *(const float4*)&g_collo[(row0 + r) * D + c];
    }
#pragma unroll
    for (int it = 0; it < 4; it++){
        int u = tid + it * 256;
        int r = u >> 4, c = (u & 15) * 8;
        *(float4*)&sBh[r][c] = *(const float4*)&g_colhi[(col0 + r) * D + c];
        *(float4*)&sBl[r][c] = *(const float4*)&g_collo[(col0 + r) * D + c];
    }
    __syncthreads();

    const int wr = wid & 3, wc = wid >> 2;
    Frag64 F;
    mma_tile64(F, sAh, sAl, sBh, sBl, wr, wc, lane);

    const int g = lane >> 2, t = lane & 3;
#pragma unroll
    for (int mf = 0; mf < 2; mf++){
        int rA = row0 + wr * 32 + mf * 16 + g;
#pragma unroll
        for (int nf = 0; nf < 4; nf++){
            int cc = col0 + wc * 32 + nf * 8 + 2 * t;
            *(float2*)&g_sim[(size_t)rA * N + cc]       = make_float2(F.c0[mf][nf], F.c1[mf][nf]);
            *(float2*)&g_sim[(size_t)(rA + 8) * N + cc] = make_float2(F.c2[mf][nf], F.c3[mf][nf]);
        }
    }

    if (bx != by){
        float* stg = (float*)(sm + OFF_AH);   // [64][132]
        __syncthreads();
#pragma unroll
        for (int mf = 0; mf < 2; mf++){
            int rr = wr * 32 + mf * 16 + g;
#pragma unroll
            for (int nf = 0; nf < 4; nf++){
                int cc = wc * 32 + nf * 8 + 2 * t;
                stg[(cc    ) * 132 + rr]     = F.c0[mf][nf];
                stg[(cc + 1) * 132 + rr]     = F.c1[mf][nf];
                stg[(cc    ) * 132 + rr + 8] = F.c2[mf][nf];
                stg[(cc + 1) * 132 + rr + 8] = F.c3[mf][nf];
            }
        }
        __syncthreads();
#pragma unroll
        for (int it = 0; it < 8; it++){
            int u = tid + it * 256;
            int r = u >> 5, c4 = (u & 31) * 4;
            float4 v = *(const float4*)&stg[r * 132 + c4];
            *(float4*)&g_sim[(size_t)(col0 + r) * N + row0 + c4] = v;
        }
    }
}

// ---------------- reward (stream B): pure, writes g_reward ----------------
__global__ __launch_bounds__(256) void reward_ap(const int* __restrict__ rl){
    __shared__ float tP[MAXPR];
    __shared__ float qv[2 * MAXPR + 4];
    __shared__ float sQ[2 * MAXPR + 4];
    __shared__ int   np_s;
    __shared__ float s_ap;

    const int tid = threadIdx.x, lane = tid & 31;
    const int i = blockIdx.x;
    const int c = rl[i];
    const float* row = g_sim + (size_t)i * N;

    if (tid == 0){ np_s = 0; s_ap = 0.f; }
    if (tid < 2 * MAXPR + 4){ sQ[tid] = 0.f; qv[tid] = -1e30f; }
    __syncthreads();

    {
        int s0 = g_startL[c], cnt = g_startL[c + 1] - s0;
        if (tid < cnt){
            int j = g_memL[s0 + tid];
            if (j != i){
                float t = binval(row[j]);
                int k = atomicAdd(&np_s, 1);
                if (k < MAXPR){
                    tP[k] = t;
                    float e = floorf(t);
                    qv[2*k]   = e + 1.0f;
                    qv[2*k+1] = e + 2.0f;
                }
            }
        }
    }
    __syncthreads();
    const int npos = min(np_s, MAXPR);
    const int K4 = (2 * npos + 3) & ~3;

    float t[16];
#pragma unroll
    for (int it = 0; it < 4; it++){
        int j4 = tid + it * 256;
        float4 v = *((const float4*)row + j4);
        int j = j4 * 4;
        t[it*4+0] = (j+0 == i) ? 1e30f : binval(v.x);
        t[it*4+1] = (j+1 == i) ? 1e30f : binval(v.y);
        t[it*4+2] = (j+2 == i) ? 1e30f : binval(v.z);
        t[it*4+3] = (j+3 == i) ? 1e30f : binval(v.w);
    }

    for (int k = 0; k < K4; k += 4){
        float q0 = qv[k], q1 = qv[k+1], q2 = qv[k+2], q3 = qv[k+3];
        float a0 = 0.f, a1 = 0.f, a2 = 0.f, a3 = 0.f;
        float b0 = 0.f, b1 = 0.f, b2 = 0.f, b3 = 0.f;
#pragma unroll
        for (int m = 0; m < 16; m += 2){
            a0 += __saturatef(q0 - t[m]);   b0 += __saturatef(q0 - t[m+1]);
            a1 += __saturatef(q1 - t[m]);   b1 += __saturatef(q1 - t[m+1]);
            a2 += __saturatef(q2 - t[m]);   b2 += __saturatef(q2 - t[m+1]);
            a3 += __saturatef(q3 - t[m]);   b3 += __saturatef(q3 - t[m+1]);
        }
        a0 += b0; a1 += b1; a2 += b2; a3 += b3;
#pragma unroll
        for (int o = 16; o; o >>= 1){
            a0 += __shfl_down_sync(0xffffffffu, a0, o);
            a1 += __shfl_down_sync(0xffffffffu, a1, o);
            a2 += __shfl_down_sync(0xffffffffu, a2, o);
            a3 += __shfl_down_sync(0xffffffffu, a3, o);
        }
        if (lane == 0){
            atomicAdd(&sQ[k],   a0);
            atomicAdd(&sQ[k+1], a1);
            atomicAdd(&sQ[k+2], a2);
            atomicAdd(&sQ[k+3], a3);
        }
    }
    __syncthreads();

    if (tid < npos){
        float tp = tP[tid];
        float e  = floorf(tp);
        float fr = tp - e;
        float u0 = e + 1.0f, u1 = e + 2.0f;
        float HP0 = 0.f, HP1 = 0.f;
        for (int q = 0; q < npos; q++){
            float tq = tP[q];
            HP0 += __saturatef(u0 - tq);
            HP1 += __saturatef(u1 - tq);
        }
        float HA0 = sQ[2*tid], HA1 = sQ[2*tid+1];
        float term = 0.f;
        if (HA0 > 0.f) term += (1.0f - fr) * HP0 / HA0;
        if (fr > 0.f && HA1 > 0.f) term += fr * HP1 / HA1;
        atomicAdd(&s_ap, term);
    }
    __syncthreads();
    if (tid == 0){
        int np = g_cntL[c] - 1;
        g_reward[i] = (np > 0) ? s_ap / (float)np : 0.f;
    }
}

// ---------------- finish (join): loss fix + weighted accumulate ----------------
__global__ __launch_bounds__(256) void finish_kernel(
    const int* __restrict__ tc, const int* __restrict__ tr)
{
    const int warp = threadIdx.x >> 5, lane = threadIdx.x & 31;
    const int i = blockIdx.x * 8 + warp;
    float nthr = fdec(g_nmax[i]) + 0.1f;
    float pt   = g_pt[i];
    int   ns   = g_lposn[i];
    float fix = 0.f;
    for (int k = lane; k < ns; k += 32){
        float v = g_lposv[(size_t)i * MAXS + k];
        int   j = g_lposj[(size_t)i * MAXS + k];
        if (v > pt) fix -= v;
        if (j != i && v < nthr) fix += 1.0f - v;
    }
    fix = wredsum(fix);
    if (lane == 0){
        int c = tc[i];
        int npos = g_cntR[c] - ((tr[i] == c) ? 1 : 0);
        float loss = (npos > 0) ? g_negsum[i] + fix : 0.f;
        atomicAdd(&g_outsum, loss * (1.0f - g_reward[i]));
    }
}

// ---------------- final scalar ----------------
__global__ void final_kernel(float* __restrict__ out){
    out[0] = g_outsum / (float)N;
}

// ---------------- launch: fork stream B for sym+reward ----------------
extern "C" void kernel_launch(void* const* d_in, const int* in_sizes, int n_in,
                              void* d_out, int out_size)
{
    const float* inputs_col    = (const float*)d_in[0];
    const int*   targets_col   = (const int*)  d_in[1];
    const float* inputs_row    = (const float*)d_in[2];
    const int*   targets_row   = (const int*)  d_in[3];
    const int*   reward_labels = (const int*)  d_in[4];
    float* out = (float*)d_out;

    static cudaStream_t sB = nullptr;
    static cudaEvent_t evFork = nullptr, evJoin = nullptr;
    if (!sB){
        cudaStreamCreateWithFlags(&sB, cudaStreamNonBlocking);
        cudaEventCreateWithFlags(&evFork, cudaEventDisableTiming);
        cudaEventCreateWithFlags(&evJoin, cudaEventDisableTiming);
        cudaFuncSetAttribute(gemm_loss, cudaFuncAttributeMaxDynamicSharedMemorySize, GL_SMEM);
        cudaFuncSetAttribute(gemm_sym,  cudaFuncAttributeMaxDynamicSharedMemorySize, GS_SMEM);
    }

    // main (capture) stream: prep
    prep_kernel<<<1025, 512>>>(targets_row, reward_labels, inputs_col, inputs_row);

    // fork
    cudaEventRecord(evFork, 0);
    cudaStreamWaitEvent(sB, evFork, 0);

    // stream A (main): loss chain
    posdot_loss<<<512, 256>>>(targets_col, inputs_col, inputs_row);
    gemm_loss<<<dim3(64, 32), 256, GL_SMEM>>>(targets_col, targets_row);

    // stream B: reward chain
    gemm_sym<<<dim3(528, 2), 256, GS_SMEM, sB>>>();
    reward_ap<<<4096, 256, 0, sB>>>(reward_labels);

    // join
    cudaEventRecord(evJoin, sB);
    cudaStreamWaitEvent(0, evJoin, 0);

    finish_kernel<<<512, 256>>>(targets_col, targets_row);
    final_kernel<<<1, 1>>>(out);
}